// round 12
// baseline (speedup 1.0000x reference)
#include <cuda_runtime.h>
#include <math.h>
#include <stdint.h>

// Problem dims (fixed by the dataset)
#define N_ROWS 32768
#define LATENT 256
#define N_ANCH 4096
#define FDIM   768

// Screen uses first KP=192 dims (partial dist^2 is a lower bound; c2f<0 =>
// e_partial >= e_full => unconditionally conservative screen).
#define KP 192
#define BM 128
#define BN 128
#define BKB 96                      // s8 k-chunk BYTES (= 96 dims)
#define NCHUNK 2
#define THREADS 512

// int8 scale: q = round(16*x). Exact integer dot; quantization error on
// dist^2 has sigma ~0.7 (5-sigma = 3.5). Flag at e > -160 (dist^2 < ~221.9);
// a truly-nonzero pair needs full dist^2 < ~208 => partial <= 208 => est <=
// ~211.5 => always flagged. Spurious flags ~5e-7 -> exact fp32 fallback.
#define QSCALE 16.0f
#define ETHR (-160.0f)

// SMEM: row stride 112 B (96 data + 16 pad). 112 = 16*7, odd multiplier mod
// 128 -> 8 consecutive rows hit 8 distinct 16B bank-groups: ldmatrix phases
// and cp.async STS conflict-free.
#define RSTRIDE_B   112
#define ATILE_B     (BM * RSTRIDE_B)           // 14336
#define STAGE_B     (2 * ATILE_B)              // 28672 (A then B)
#define SM_OFF_ZQ   0
#define SM_OFF_AQ   512
#define SM_OFF_ST   1024
#define SMEM_DYN    (SM_OFF_ST + 2 * STAGE_B)  // 58368 -> occ=2

// Scratch (device globals: allocation-free per harness rules)
__device__ float   g_zsq[N_ROWS];              // partial (KP-dim) sq-norms
__device__ float   g_asq[N_ANCH];
__device__ int8_t  g_z8[(size_t)N_ROWS * KP];
__device__ int8_t  g_a8[(size_t)N_ANCH * KP];

__device__ __forceinline__ uint32_t smem_u32(const void* p) {
    uint32_t a;
    asm("{ .reg .u64 t; cvta.to.shared.u64 t, %1; cvt.u32.u64 %0, t; }"
        : "=r"(a) : "l"(p));
    return a;
}
__device__ __forceinline__ void cp_async16(uint32_t dst, const void* src) {
    asm volatile("cp.async.cg.shared.global [%0], [%1], 16;"
                 :: "r"(dst), "l"(src));
}
#define CP_COMMIT() asm volatile("cp.async.commit_group;" ::: "memory")
#define CP_WAITN(n) asm volatile("cp.async.wait_group %0;" :: "n"(n) : "memory")

__device__ __forceinline__ void ldsm_x4(uint32_t& r0, uint32_t& r1,
                                        uint32_t& r2, uint32_t& r3,
                                        uint32_t addr) {
    asm volatile("ldmatrix.sync.aligned.m8n8.x4.shared.b16 {%0,%1,%2,%3}, [%4];"
                 : "=r"(r0), "=r"(r1), "=r"(r2), "=r"(r3) : "r"(addr));
}
// INT8 IMMA k=32, s32 accumulators (accum layout == f32 layout of k16.f16).
__device__ __forceinline__ void mma_s8(int& c0, int& c1, int& c2, int& c3,
                                       uint32_t a0, uint32_t a1, uint32_t a2, uint32_t a3,
                                       uint32_t b0, uint32_t b1) {
    asm volatile("mma.sync.aligned.m16n8k32.row.col.s32.s8.s8.s32 "
                 "{%0,%1,%2,%3}, {%4,%5,%6,%7}, {%8,%9}, {%0,%1,%2,%3};"
                 : "+r"(c0), "+r"(c1), "+r"(c2), "+r"(c3)
                 : "r"(a0), "r"(a1), "r"(a2), "r"(a3), "r"(b0), "r"(b1));
}

__device__ __forceinline__ int q8(float v) {
    int q = __float2int_rn(v * QSCALE);
    return max(-127, min(127, q));
}

// ---------------------------------------------------------------------------
// Merged prepass: blocks [0, ZBLK) zero the output; blocks [ZBLK, ...) do
// fp32 -> s8 (first KP dims) + partial sq-norms (one warp per row).
// ---------------------------------------------------------------------------
#define ZBLK 6144
__global__ void rkhs_prep(const float* __restrict__ z,
                          const float* __restrict__ anch,
                          float4* __restrict__ out) {
    if (blockIdx.x < ZBLK) {
        const int nth = ZBLK * 256;
        int i = blockIdx.x * 256 + threadIdx.x;
#pragma unroll
        for (int j = 0; j < 4; j++)
            out[i + j * nth] = make_float4(0.f, 0.f, 0.f, 0.f);
        return;
    }
    int gw   = ((blockIdx.x - ZBLK) * blockDim.x + threadIdx.x) >> 5;
    int lane = threadIdx.x & 31;
    if (gw >= N_ROWS + N_ANCH) return;

    const float* src;
    uint32_t*    dst8;
    float*       dsq;
    if (gw < N_ROWS) {
        src  = z + (size_t)gw * LATENT;
        dst8 = (uint32_t*)(g_z8 + (size_t)gw * KP);
        dsq  = &g_zsq[gw];
    } else {
        int r = gw - N_ROWS;
        src  = anch + (size_t)r * LATENT;
        dst8 = (uint32_t*)(g_a8 + (size_t)r * KP);
        dsq  = &g_asq[r];
    }

    const float4* p = (const float4*)src;
    float s = 0.f;
#pragma unroll
    for (int i = 0; i < 2; i++) {
        int j = lane + i * 32;                  // float4 index
        if (j < KP / 4) {                       // first 48 of 64
            float4 v = p[j];
            s += v.x * v.x + v.y * v.y + v.z * v.z + v.w * v.w;
            uint32_t w = ((uint32_t)(uint8_t)(int8_t)q8(v.x))
                       | ((uint32_t)(uint8_t)(int8_t)q8(v.y) << 8)
                       | ((uint32_t)(uint8_t)(int8_t)q8(v.z) << 16)
                       | ((uint32_t)(uint8_t)(int8_t)q8(v.w) << 24);
            dst8[j] = w;
        }
    }
#pragma unroll
    for (int o = 16; o; o >>= 1) s += __shfl_xor_sync(0xffffffffu, s, o);
    if (lane == 0) *dsq = s;
}

// ---------------------------------------------------------------------------
// cp.async: k-chunk c (96 B) -> stage s. 1536 16B jobs (768 A + 768 B);
// 3 per thread. Gmem s8 row = KP = 192 B.
// ---------------------------------------------------------------------------
__device__ __forceinline__ void load_stage(char* smem, int s, int c,
                                           const char* gA, const char* gB,
                                           int tid) {
    char* stA = smem + SM_OFF_ST + s * STAGE_B;
    char* stB = stA + ATILE_B;
    const uint32_t cb = (uint32_t)c * BKB;
#pragma unroll
    for (int i = 0; i < 3; i++) {
        int job = tid + i * THREADS;            // 0..1535
        int jj  = (job >= 768) ? job - 768 : job;
        int r   = jj / 6;
        int cc  = jj - r * 6;
        uint32_t soff = (uint32_t)r * RSTRIDE_B + (uint32_t)cc * 16;
        size_t   goff = (size_t)r * KP + cb + (uint32_t)cc * 16;
        if (job < 768) cp_async16(smem_u32(stA + soff), gA + goff);
        else           cp_async16(smem_u32(stB + soff), gB + goff);
    }
}

// ---------------------------------------------------------------------------
// Main: s8 IMMA screening GEMM (128x128x192 per CTA), 2 chunks of k=96,
// warp grid 4x4, warp tile 32x32. Addressing identical to the proven bf16
// kernel (ldmatrix.b16 reg = 4 consecutive s8 = exactly the imma fragment).
// ---------------------------------------------------------------------------
__global__ __launch_bounds__(THREADS, 2)
void rkhs_main(const float* __restrict__ z,
               const float* __restrict__ anch,
               const float* __restrict__ alpha,
               const float* __restrict__ logls,
               float* __restrict__ out) {
    extern __shared__ char smem[];
    const uint32_t sb = smem_u32(smem);

    const int m0   = blockIdx.y * BM;
    const int c0   = blockIdx.x * BN;
    const int tid  = threadIdx.x;
    const int wid  = tid >> 5;
    const int lane = tid & 31;
    const int wm   = wid & 3;
    const int wn   = wid >> 2;

    const char* gA = (const char*)(g_z8 + (size_t)m0 * KP);
    const char* gB = (const char*)(g_a8 + (size_t)c0 * KP);

    // Stage norms (latency overlaps prologue cp.asyncs).
    if (tid < 128)      ((float*)(smem + SM_OFF_ZQ))[tid]       = g_zsq[m0 + tid];
    else if (tid < 256) ((float*)(smem + SM_OFF_AQ))[tid - 128] = g_asq[c0 + tid - 128];

    // Prologue: chunk 0 -> stage 0, chunk 1 -> stage 1.
    load_stage(smem, 0, 0, gA, gB, tid); CP_COMMIT();
    load_stage(smem, 1, 1, gA, gB, tid); CP_COMMIT();

    // Fragment bases (A then B per stage); same lane mapping as bf16 kernel.
    const uint32_t aOff = (uint32_t)(wm * 32 + (lane & 15)) * RSTRIDE_B
                        + (uint32_t)(lane >> 4) * 16;
    const uint32_t bOff = (uint32_t)(wn * 32 + ((lane >> 4) << 3) + (lane & 7)) * RSTRIDE_B
                        + (uint32_t)((lane >> 3) & 1) * 16;

    int c[2][4][4];
#pragma unroll
    for (int mi = 0; mi < 2; mi++)
#pragma unroll
        for (int ni = 0; ni < 4; ni++)
#pragma unroll
            for (int q = 0; q < 4; q++) c[mi][ni][q] = 0;

#pragma unroll
    for (int ch = 0; ch < NCHUNK; ch++) {
        if (ch == 0) CP_WAITN(1); else CP_WAITN(0);
        __syncthreads();

        const uint32_t stA = sb + SM_OFF_ST + (uint32_t)ch * STAGE_B;
        const uint32_t stB = stA + ATILE_B;
        const uint32_t aB  = stA + aOff;
        const uint32_t bB  = stB + bOff;

#pragma unroll
        for (int kt = 0; kt < BKB / 32; kt++) {    // 3 k32-steps per chunk
            const uint32_t ko = (uint32_t)kt * 32; // 32 s8 = 32 B
            uint32_t a[2][4], b[2][4];
            ldsm_x4(a[0][0], a[0][1], a[0][2], a[0][3], aB + ko);
            ldsm_x4(a[1][0], a[1][1], a[1][2], a[1][3], aB + ko + 16u * RSTRIDE_B);
            ldsm_x4(b[0][0], b[0][1], b[0][2], b[0][3], bB + ko);
            ldsm_x4(b[1][0], b[1][1], b[1][2], b[1][3], bB + ko + 16u * RSTRIDE_B);
#pragma unroll
            for (int mi = 0; mi < 2; mi++)
#pragma unroll
                for (int ni = 0; ni < 4; ni++)
                    mma_s8(c[mi][ni][0], c[mi][ni][1], c[mi][ni][2], c[mi][ni][3],
                           a[mi][0], a[mi][1], a[mi][2], a[mi][3],
                           b[ni >> 1][(ni & 1) * 2], b[ni >> 1][(ni & 1) * 2 + 1]);
        }
    }

    // --- Screening epilogue (cross = dot_s32 / QSCALE^2) ---
    const float lsv = logls[0];
    const float l   = expf(lsv);
    const float il2 = 1.0f / (l * l + 1e-7f);
    const float c2f = -0.5f * 1.44269504088896340736f * il2;
    const float qs2 = 1.0f / (QSCALE * QSCALE);

    const float* sZq = (const float*)(smem + SM_OFF_ZQ);
    const float* sAq = (const float*)(smem + SM_OFF_AQ);
    const int rBase = wm * 32 + (lane >> 2);
    const int nBase = wn * 32 + 2 * (lane & 3);

    int any_local = 0;
#pragma unroll
    for (int mi = 0; mi < 2; mi++) {
        float zq0 = sZq[rBase + mi * 16];
        float zq1 = sZq[rBase + mi * 16 + 8];
#pragma unroll
        for (int ni = 0; ni < 4; ni++) {
            float aq0 = sAq[nBase + ni * 8];
            float aq1 = sAq[nBase + ni * 8 + 1];
            float e0 = c2f * (zq0 + aq0 - 2.f * qs2 * (float)c[mi][ni][0]);
            float e1 = c2f * (zq0 + aq1 - 2.f * qs2 * (float)c[mi][ni][1]);
            float e2 = c2f * (zq1 + aq0 - 2.f * qs2 * (float)c[mi][ni][2]);
            float e3 = c2f * (zq1 + aq1 - 2.f * qs2 * (float)c[mi][ni][3]);
            any_local |= (e0 > ETHR) | (e1 > ETHR) | (e2 > ETHR) | (e3 > ETHR);
        }
    }

    if (!__syncthreads_or(any_local)) return;

    // Exact fp32 fallback over ALL 256 dims for flagged pairs (cold path).
#pragma unroll 1
    for (int mi = 0; mi < 2; mi++) {
#pragma unroll 1
        for (int ni = 0; ni < 4; ni++) {
#pragma unroll 1
            for (int q = 0; q < 4; q++) {
                int rl = rBase + mi * 16 + (q >> 1) * 8;
                int nl = nBase + ni * 8 + (q & 1);
                float e = c2f * (sZq[rl] + sAq[nl] - 2.f * qs2 * (float)c[mi][ni][q]);
                if (e > ETHR) {
                    int gr = m0 + rl;
                    int gc = c0 + nl;
                    const float* zr = z    + (size_t)gr * LATENT;
                    const float* ar = anch + (size_t)gc * LATENT;
                    float dot = 0.f, zq = 0.f, aq = 0.f;
                    for (int k = 0; k < LATENT; k++) {
                        dot = fmaf(zr[k], ar[k], dot);
                        zq  = fmaf(zr[k], zr[k], zq);
                        aq  = fmaf(ar[k], ar[k], aq);
                    }
                    float de = fmaxf(zq + aq - 2.f * dot, 0.f);
                    float p  = expf(-0.5f * de * il2);
                    if (p != 0.f) {
                        const float* al = alpha + (size_t)gc * FDIM;
                        float*       o  = out   + (size_t)gr * FDIM;
                        for (int f = 0; f < FDIM; f++) atomicAdd(&o[f], p * al[f]);
                    }
                }
            }
        }
    }
}

// ---------------------------------------------------------------------------
extern "C" void kernel_launch(void* const* d_in, const int* in_sizes, int n_in,
                              void* d_out, int out_size) {
    const float* z     = (const float*)d_in[0];
    const float* anch  = (const float*)d_in[1];
    const float* alpha = (const float*)d_in[2];
    const float* logls = (const float*)d_in[3];
    float*       out   = (float*)d_out;

    cudaFuncSetAttribute(rkhs_main,
                         cudaFuncAttributeMaxDynamicSharedMemorySize, SMEM_DYN);

    // Merged zero + quantize/norm prepass.
    int pblk = ((N_ROWS + N_ANCH) * 32 + 255) / 256;   // 4608
    rkhs_prep<<<ZBLK + pblk, 256>>>(z, anch, (float4*)d_out);

    dim3 grid(N_ANCH / BN, N_ROWS / BM);               // (32, 256)
    rkhs_main<<<grid, THREADS, SMEM_DYN>>>(z, anch, alpha, logls, out);
}

// round 13
// speedup vs baseline: 1.5524x; 1.5524x over previous
#include <cuda_runtime.h>
#include <cuda_bf16.h>
#include <math.h>
#include <stdint.h>

// Problem dims (fixed by the dataset)
#define N_ROWS 32768
#define LATENT 256
#define N_ANCH 4096
#define FDIM   768

// Screen uses first KP=192 dims (partial dist^2 lower-bounds full dist^2;
// c2f < 0 => e_partial >= e_full => unconditionally conservative screen).
#define KP 192
#define BM 128
#define BN 128
#define THREADS 512

// Flag if e_partial > -170 (log2; fp32 exp nonzero needs e_full > ~-150).
// Flagged pairs -> exact fp32 recompute over ALL 256 dims.
#define ETHR (-170.0f)

// SMEM: full-K tiles. Row = 192 bf16 = 384 B data + 16 pad = 400 B stride.
// 400 mod 128 = 16 -> 8 consecutive rows hit 8 distinct 16B bank-groups:
// ldmatrix phases conflict-free.
#define RSTRIDE_B   400
#define ATILE_B     (BM * RSTRIDE_B)          // 51200
#define SM_OFF_ZQ   0
#define SM_OFF_AQ   512
#define SM_OFF_ST   1024
#define SMEM_DYN    (SM_OFF_ST + 2 * ATILE_B) // 103424 -> occ=2 (206.8KB/SM)

// Scratch (device globals: allocation-free per harness rules)
__device__ float         g_zsq[N_ROWS];       // partial (KP-dim) sq-norms
__device__ float         g_asq[N_ANCH];
__device__ __nv_bfloat16 g_zb[(size_t)N_ROWS * KP];
__device__ __nv_bfloat16 g_ab[(size_t)N_ANCH * KP];

__device__ __forceinline__ uint32_t smem_u32(const void* p) {
    uint32_t a;
    asm("{ .reg .u64 t; cvta.to.shared.u64 t, %1; cvt.u32.u64 %0, t; }"
        : "=r"(a) : "l"(p));
    return a;
}
__device__ __forceinline__ void cp_async16(uint32_t dst, const void* src) {
    asm volatile("cp.async.cg.shared.global [%0], [%1], 16;"
                 :: "r"(dst), "l"(src));
}
#define CP_COMMIT() asm volatile("cp.async.commit_group;" ::: "memory")
#define CP_WAIT0()  asm volatile("cp.async.wait_group 0;" ::: "memory")

__device__ __forceinline__ void ldsm_x4(uint32_t& r0, uint32_t& r1,
                                        uint32_t& r2, uint32_t& r3,
                                        uint32_t addr) {
    asm volatile("ldmatrix.sync.aligned.m8n8.x4.shared.b16 {%0,%1,%2,%3}, [%4];"
                 : "=r"(r0), "=r"(r1), "=r"(r2), "=r"(r3) : "r"(addr));
}
__device__ __forceinline__ void mma_16816(float& c0, float& c1, float& c2, float& c3,
                                          uint32_t a0, uint32_t a1, uint32_t a2, uint32_t a3,
                                          uint32_t b0, uint32_t b1) {
    asm volatile("mma.sync.aligned.m16n8k16.row.col.f32.bf16.bf16.f32 "
                 "{%0,%1,%2,%3}, {%4,%5,%6,%7}, {%8,%9}, {%0,%1,%2,%3};"
                 : "+f"(c0), "+f"(c1), "+f"(c2), "+f"(c3)
                 : "r"(a0), "r"(a1), "r"(a2), "r"(a3), "r"(b0), "r"(b1));
}

// ---------------------------------------------------------------------------
// Merged prepass: blocks [0, ZBLK) zero the output; blocks [ZBLK, ...) do
// fp32 -> bf16 (first KP dims) + partial sq-norms (one warp per row).
// ---------------------------------------------------------------------------
#define ZBLK 6144
__global__ void rkhs_prep(const float* __restrict__ z,
                          const float* __restrict__ anch,
                          float4* __restrict__ out) {
    if (blockIdx.x < ZBLK) {
        const int nth = ZBLK * 256;
        int i = blockIdx.x * 256 + threadIdx.x;
#pragma unroll
        for (int j = 0; j < 4; j++)
            out[i + j * nth] = make_float4(0.f, 0.f, 0.f, 0.f);
        return;
    }
    int gw   = ((blockIdx.x - ZBLK) * blockDim.x + threadIdx.x) >> 5;
    int lane = threadIdx.x & 31;
    if (gw >= N_ROWS + N_ANCH) return;

    const float*    src;
    __nv_bfloat162* dstb;
    float*          dsq;
    if (gw < N_ROWS) {
        src  = z + (size_t)gw * LATENT;
        dstb = (__nv_bfloat162*)(g_zb + (size_t)gw * KP);
        dsq  = &g_zsq[gw];
    } else {
        int r = gw - N_ROWS;
        src  = anch + (size_t)r * LATENT;
        dstb = (__nv_bfloat162*)(g_ab + (size_t)r * KP);
        dsq  = &g_asq[r];
    }

    const float4* p = (const float4*)src;
    float s = 0.f;
#pragma unroll
    for (int i = 0; i < 2; i++) {
        int j = lane + i * 32;                  // float4 index
        if (j < KP / 4) {                       // first 48 of 64
            float4 v = p[j];
            s += v.x * v.x + v.y * v.y + v.z * v.z + v.w * v.w;
            dstb[2 * j + 0] = __floats2bfloat162_rn(v.x, v.y);
            dstb[2 * j + 1] = __floats2bfloat162_rn(v.z, v.w);
        }
    }
#pragma unroll
    for (int o = 16; o; o >>= 1) s += __shfl_xor_sync(0xffffffffu, s, o);
    if (lane == 0) *dsq = s;
}

// ---------------------------------------------------------------------------
// Main: bf16 mma.sync screening GEMM (128x128x192 per CTA). Full K resident
// in SMEM: ONE cp.async fill + ONE barrier, then 12 uninterrupted k-steps.
// Warp grid 4x4, warp tile 32x32; occ=2 overlaps fill with peer-CTA compute.
// ---------------------------------------------------------------------------
__global__ __launch_bounds__(THREADS, 2)
void rkhs_main(const float* __restrict__ z,
               const float* __restrict__ anch,
               const float* __restrict__ alpha,
               const float* __restrict__ logls,
               float* __restrict__ out) {
    extern __shared__ char smem[];
    const uint32_t sb = smem_u32(smem);

    const int m0   = blockIdx.y * BM;
    const int c0   = blockIdx.x * BN;
    const int tid  = threadIdx.x;
    const int wid  = tid >> 5;
    const int lane = tid & 31;
    const int wm   = wid & 3;
    const int wn   = wid >> 2;

    const char* gA = (const char*)(g_zb + (size_t)m0 * KP);
    const char* gB = (const char*)(g_ab + (size_t)c0 * KP);
    char* stA = smem + SM_OFF_ST;
    char* stB = stA + ATILE_B;

    // Stage norms (latency overlaps the cp.async fill below).
    if (tid < 128)      ((float*)(smem + SM_OFF_ZQ))[tid]       = g_zsq[m0 + tid];
    else if (tid < 256) ((float*)(smem + SM_OFF_AQ))[tid - 128] = g_asq[c0 + tid - 128];

    // Single full-K fill: 3072 16B jobs per tile, 12 jobs/thread total.
#pragma unroll
    for (int i = 0; i < 6; i++) {
        int job = tid + i * THREADS;            // 0..3071
        int r   = job / 24;
        int cc  = job - r * 24;
        uint32_t soff = (uint32_t)r * RSTRIDE_B + (uint32_t)cc * 16;
        size_t   goff = (size_t)r * (KP * 2) + (uint32_t)cc * 16;
        cp_async16(smem_u32(stA + soff), gA + goff);
        cp_async16(smem_u32(stB + soff), gB + goff);
    }
    CP_COMMIT();
    CP_WAIT0();
    __syncthreads();

    // Fragment bases; same lane mapping as the proven R8/R11 kernels.
    const uint32_t aB = sb + (uint32_t)SM_OFF_ST
        + (uint32_t)(wm * 32 + (lane & 15)) * RSTRIDE_B + (uint32_t)(lane >> 4) * 16;
    const uint32_t bB = sb + (uint32_t)SM_OFF_ST + (uint32_t)ATILE_B
        + (uint32_t)(wn * 32 + ((lane >> 4) << 3) + (lane & 7)) * RSTRIDE_B
        + (uint32_t)((lane >> 3) & 1) * 16;

    float c[2][4][4];
#pragma unroll
    for (int mi = 0; mi < 2; mi++)
#pragma unroll
        for (int ni = 0; ni < 4; ni++)
#pragma unroll
            for (int q = 0; q < 4; q++) c[mi][ni][q] = 0.f;

#pragma unroll
    for (int kt = 0; kt < KP / 16; kt++) {      // 12 uninterrupted k-steps
        const uint32_t ko = (uint32_t)kt * 32;
        uint32_t a[2][4], b[2][4];
        ldsm_x4(a[0][0], a[0][1], a[0][2], a[0][3], aB + ko);
        ldsm_x4(a[1][0], a[1][1], a[1][2], a[1][3], aB + ko + 16u * RSTRIDE_B);
        ldsm_x4(b[0][0], b[0][1], b[0][2], b[0][3], bB + ko);
        ldsm_x4(b[1][0], b[1][1], b[1][2], b[1][3], bB + ko + 16u * RSTRIDE_B);
#pragma unroll
        for (int mi = 0; mi < 2; mi++)
#pragma unroll
            for (int ni = 0; ni < 4; ni++)
                mma_16816(c[mi][ni][0], c[mi][ni][1], c[mi][ni][2], c[mi][ni][3],
                          a[mi][0], a[mi][1], a[mi][2], a[mi][3],
                          b[ni >> 1][(ni & 1) * 2], b[ni >> 1][(ni & 1) * 2 + 1]);
    }

    // --- Screening epilogue (acc: row = lane>>2 (+8 q>=2), col = 2*(lane&3) (+1 odd q)) ---
    const float lsv = logls[0];
    const float l   = expf(lsv);
    const float il2 = 1.0f / (l * l + 1e-7f);
    const float c2f = -0.5f * 1.44269504088896340736f * il2;

    const float* sZq = (const float*)(smem + SM_OFF_ZQ);
    const float* sAq = (const float*)(smem + SM_OFF_AQ);
    const int rBase = wm * 32 + (lane >> 2);
    const int nBase = wn * 32 + 2 * (lane & 3);

    int any_local = 0;
#pragma unroll
    for (int mi = 0; mi < 2; mi++) {
        float zq0 = sZq[rBase + mi * 16];
        float zq1 = sZq[rBase + mi * 16 + 8];
#pragma unroll
        for (int ni = 0; ni < 4; ni++) {
            float aq0 = sAq[nBase + ni * 8];
            float aq1 = sAq[nBase + ni * 8 + 1];
            float e0 = c2f * (zq0 + aq0 - 2.f * c[mi][ni][0]);
            float e1 = c2f * (zq0 + aq1 - 2.f * c[mi][ni][1]);
            float e2 = c2f * (zq1 + aq0 - 2.f * c[mi][ni][2]);
            float e3 = c2f * (zq1 + aq1 - 2.f * c[mi][ni][3]);
            any_local |= (e0 > ETHR) | (e1 > ETHR) | (e2 > ETHR) | (e3 > ETHR);
        }
    }

    // ~6e-6 flag rate (2*chi2_192 left tail) -> virtually every CTA exits.
    if (!__syncthreads_or(any_local)) return;

    // Exact fp32 fallback over ALL 256 dims for flagged pairs (cold path).
#pragma unroll 1
    for (int mi = 0; mi < 2; mi++) {
#pragma unroll 1
        for (int ni = 0; ni < 4; ni++) {
#pragma unroll 1
            for (int q = 0; q < 4; q++) {
                int rl = rBase + mi * 16 + (q >> 1) * 8;
                int nl = nBase + ni * 8 + (q & 1);
                float e = c2f * (sZq[rl] + sAq[nl] - 2.f * c[mi][ni][q]);
                if (e > ETHR) {
                    int gr = m0 + rl;
                    int gc = c0 + nl;
                    const float* zr = z    + (size_t)gr * LATENT;
                    const float* ar = anch + (size_t)gc * LATENT;
                    float dot = 0.f, zq = 0.f, aq = 0.f;
                    for (int k = 0; k < LATENT; k++) {
                        dot = fmaf(zr[k], ar[k], dot);
                        zq  = fmaf(zr[k], zr[k], zq);
                        aq  = fmaf(ar[k], ar[k], aq);
                    }
                    float de = fmaxf(zq + aq - 2.f * dot, 0.f);
                    float p  = expf(-0.5f * de * il2);
                    if (p != 0.f) {
                        const float* al = alpha + (size_t)gc * FDIM;
                        float*       o  = out   + (size_t)gr * FDIM;
                        for (int f = 0; f < FDIM; f++) atomicAdd(&o[f], p * al[f]);
                    }
                }
            }
        }
    }
}

// ---------------------------------------------------------------------------
extern "C" void kernel_launch(void* const* d_in, const int* in_sizes, int n_in,
                              void* d_out, int out_size) {
    const float* z     = (const float*)d_in[0];
    const float* anch  = (const float*)d_in[1];
    const float* alpha = (const float*)d_in[2];
    const float* logls = (const float*)d_in[3];
    float*       out   = (float*)d_out;

    cudaFuncSetAttribute(rkhs_main,
                         cudaFuncAttributeMaxDynamicSharedMemorySize, SMEM_DYN);

    // Merged zero + convert/norm prepass.
    int pblk = ((N_ROWS + N_ANCH) * 32 + 255) / 256;   // 4608
    rkhs_prep<<<ZBLK + pblk, 256>>>(z, anch, (float4*)d_out);

    dim3 grid(N_ANCH / BN, N_ROWS / BM);               // (32, 256)
    rkhs_main<<<grid, THREADS, SMEM_DYN>>>(z, anch, alpha, logls, out);
}

// round 14
// speedup vs baseline: 1.8398x; 1.1852x over previous
#include <cuda_runtime.h>
#include <cuda_fp16.h>
#include <math.h>
#include <stdint.h>

// Problem dims (fixed by the dataset)
#define N_ROWS 32768
#define LATENT 256
#define N_ANCH 4096
#define FDIM   768

// Screen uses first KP=192 dims (partial dist^2 lower-bounds full dist^2;
// c2f < 0 => e_partial >= e_full => unconditionally conservative screen).
#define KP 192
#define BM 128
#define BN 128
#define THREADS 512

// Flag if e_partial > -160 (log2; fp32 exp nonzero needs e_full > ~-150).
// f16 compute perturbs dist^2 by <= ~3; threshold margin is >= 10. Flagged
// pairs -> exact fp32 recompute over ALL 256 dims from global memory.
#define ETHR (-160.0f)

// SMEM: full-K tiles. Row = 192 f16 = 384 B data + 16 pad = 400 B stride.
// 400 mod 128 = 16 -> 8 consecutive rows hit 8 distinct 16B bank-groups.
#define RSTRIDE_B   400
#define ATILE_B     (BM * RSTRIDE_B)          // 51200
#define SM_OFF_ZQ   0
#define SM_OFF_AQ   512
#define SM_OFF_ST   1024
#define SMEM_DYN    (SM_OFF_ST + 2 * ATILE_B) // 103424 -> occ=2

// Scratch (device globals: allocation-free per harness rules)
__device__ float  g_zsq[N_ROWS];              // partial (KP-dim) sq-norms
__device__ float  g_asq[N_ANCH];
__device__ __half g_zh[(size_t)N_ROWS * KP];
__device__ __half g_ah[(size_t)N_ANCH * KP];

__device__ __forceinline__ uint32_t smem_u32(const void* p) {
    uint32_t a;
    asm("{ .reg .u64 t; cvta.to.shared.u64 t, %1; cvt.u32.u64 %0, t; }"
        : "=r"(a) : "l"(p));
    return a;
}
__device__ __forceinline__ void cp_async16(uint32_t dst, const void* src) {
    asm volatile("cp.async.cg.shared.global [%0], [%1], 16;"
                 :: "r"(dst), "l"(src));
}
#define CP_COMMIT() asm volatile("cp.async.commit_group;" ::: "memory")
#define CP_WAIT0()  asm volatile("cp.async.wait_group 0;" ::: "memory")

__device__ __forceinline__ void ldsm_x4(uint32_t& r0, uint32_t& r1,
                                        uint32_t& r2, uint32_t& r3,
                                        uint32_t addr) {
    asm volatile("ldmatrix.sync.aligned.m8n8.x4.shared.b16 {%0,%1,%2,%3}, [%4];"
                 : "=r"(r0), "=r"(r1), "=r"(r2), "=r"(r3) : "r"(addr));
}
// f16 x f16 -> f16 accum MMA. D/C fragment = 2 b32 regs (4 f16):
//   reg0 = row (lane>>2), cols 2(lane&3)+{0,1}; reg1 = row (lane>>2)+8.
__device__ __forceinline__ void mma_f16acc(uint32_t& c0, uint32_t& c1,
                                           uint32_t a0, uint32_t a1, uint32_t a2, uint32_t a3,
                                           uint32_t b0, uint32_t b1) {
    asm volatile("mma.sync.aligned.m16n8k16.row.col.f16.f16.f16.f16 "
                 "{%0,%1}, {%2,%3,%4,%5}, {%6,%7}, {%0,%1};"
                 : "+r"(c0), "+r"(c1)
                 : "r"(a0), "r"(a1), "r"(a2), "r"(a3), "r"(b0), "r"(b1));
}

// ---------------------------------------------------------------------------
// Merged prepass: blocks [0, ZBLK) zero the output; blocks [ZBLK, ...) do
// fp32 -> f16 (first KP dims) + partial sq-norms (one warp per row).
// ---------------------------------------------------------------------------
#define ZBLK 6144
__global__ void rkhs_prep(const float* __restrict__ z,
                          const float* __restrict__ anch,
                          float4* __restrict__ out) {
    if (blockIdx.x < ZBLK) {
        const int nth = ZBLK * 256;
        int i = blockIdx.x * 256 + threadIdx.x;
#pragma unroll
        for (int j = 0; j < 4; j++)
            out[i + j * nth] = make_float4(0.f, 0.f, 0.f, 0.f);
        return;
    }
    int gw   = ((blockIdx.x - ZBLK) * blockDim.x + threadIdx.x) >> 5;
    int lane = threadIdx.x & 31;
    if (gw >= N_ROWS + N_ANCH) return;

    const float* src;
    __half2*     dsth;
    float*       dsq;
    if (gw < N_ROWS) {
        src  = z + (size_t)gw * LATENT;
        dsth = (__half2*)(g_zh + (size_t)gw * KP);
        dsq  = &g_zsq[gw];
    } else {
        int r = gw - N_ROWS;
        src  = anch + (size_t)r * LATENT;
        dsth = (__half2*)(g_ah + (size_t)r * KP);
        dsq  = &g_asq[r];
    }

    const float4* p = (const float4*)src;
    float s = 0.f;
#pragma unroll
    for (int i = 0; i < 2; i++) {
        int j = lane + i * 32;                  // float4 index
        if (j < KP / 4) {                       // first 48 of 64
            float4 v = p[j];
            s += v.x * v.x + v.y * v.y + v.z * v.z + v.w * v.w;
            dsth[2 * j + 0] = __floats2half2_rn(v.x, v.y);
            dsth[2 * j + 1] = __floats2half2_rn(v.z, v.w);
        }
    }
#pragma unroll
    for (int o = 16; o; o >>= 1) s += __shfl_xor_sync(0xffffffffu, s, o);
    if (lane == 0) *dsq = s;
}

// ---------------------------------------------------------------------------
// Main: f16 mma.sync screening GEMM (128x128x192 per CTA), f16 accumulators.
// Full K resident: ONE cp.async fill + ONE barrier + 12 k-steps.
// Warp grid 4x4, warp tile 32x32; occ=2 (32 warps/SM).
// ---------------------------------------------------------------------------
__global__ __launch_bounds__(THREADS, 2)
void rkhs_main(const float* __restrict__ z,
               const float* __restrict__ anch,
               const float* __restrict__ alpha,
               const float* __restrict__ logls,
               float* __restrict__ out) {
    extern __shared__ char smem[];
    const uint32_t sb = smem_u32(smem);

    const int m0   = blockIdx.y * BM;
    const int c0   = blockIdx.x * BN;
    const int tid  = threadIdx.x;
    const int wid  = tid >> 5;
    const int lane = tid & 31;
    const int wm   = wid & 3;
    const int wn   = wid >> 2;

    const char* gA = (const char*)(g_zh + (size_t)m0 * KP);
    const char* gB = (const char*)(g_ah + (size_t)c0 * KP);
    char* stA = smem + SM_OFF_ST;
    char* stB = stA + ATILE_B;

    // Stage norms (latency overlaps the cp.async fill below).
    if (tid < 128)      ((float*)(smem + SM_OFF_ZQ))[tid]       = g_zsq[m0 + tid];
    else if (tid < 256) ((float*)(smem + SM_OFF_AQ))[tid - 128] = g_asq[c0 + tid - 128];

    // Single full-K fill: 3072 16B jobs per tile, 12 jobs/thread total.
#pragma unroll
    for (int i = 0; i < 6; i++) {
        int job = tid + i * THREADS;            // 0..3071
        int r   = job / 24;
        int cc  = job - r * 24;
        uint32_t soff = (uint32_t)r * RSTRIDE_B + (uint32_t)cc * 16;
        size_t   goff = (size_t)r * (KP * 2) + (uint32_t)cc * 16;
        cp_async16(smem_u32(stA + soff), gA + goff);
        cp_async16(smem_u32(stB + soff), gB + goff);
    }
    CP_COMMIT();
    CP_WAIT0();
    __syncthreads();

    // Fragment bases; same lane mapping as the proven bf16 kernels.
    const uint32_t aB = sb + (uint32_t)SM_OFF_ST
        + (uint32_t)(wm * 32 + (lane & 15)) * RSTRIDE_B + (uint32_t)(lane >> 4) * 16;
    const uint32_t bB = sb + (uint32_t)SM_OFF_ST + (uint32_t)ATILE_B
        + (uint32_t)(wn * 32 + ((lane >> 4) << 3) + (lane & 7)) * RSTRIDE_B
        + (uint32_t)((lane >> 3) & 1) * 16;

    uint32_t c[2][4][2];                        // f16x2 accumulators
#pragma unroll
    for (int mi = 0; mi < 2; mi++)
#pragma unroll
        for (int ni = 0; ni < 4; ni++) { c[mi][ni][0] = 0u; c[mi][ni][1] = 0u; }

#pragma unroll
    for (int kt = 0; kt < KP / 16; kt++) {      // 12 uninterrupted k-steps
        const uint32_t ko = (uint32_t)kt * 32;
        uint32_t a[2][4], b[2][4];
        ldsm_x4(a[0][0], a[0][1], a[0][2], a[0][3], aB + ko);
        ldsm_x4(a[1][0], a[1][1], a[1][2], a[1][3], aB + ko + 16u * RSTRIDE_B);
        ldsm_x4(b[0][0], b[0][1], b[0][2], b[0][3], bB + ko);
        ldsm_x4(b[1][0], b[1][1], b[1][2], b[1][3], bB + ko + 16u * RSTRIDE_B);
#pragma unroll
        for (int mi = 0; mi < 2; mi++)
#pragma unroll
            for (int ni = 0; ni < 4; ni++)
                mma_f16acc(c[mi][ni][0], c[mi][ni][1],
                           a[mi][0], a[mi][1], a[mi][2], a[mi][3],
                           b[ni >> 1][(ni & 1) * 2], b[ni >> 1][(ni & 1) * 2 + 1]);
    }

    // --- Lean screening epilogue ---
    // flag iff e = c2f*dist > ETHR  <=>  dist < T (c2f<0, T=ETHR/c2f>0)
    //      <=> cross > 0.5*(zq + aq - T) = u_r + v_c,
    // with u_r = 0.5*zq_r - 0.25*T, v_c = 0.5*aq_c - 0.25*T.
    const float lsv = logls[0];
    const float l   = expf(lsv);
    const float il2 = 1.0f / (l * l + 1e-7f);
    const float c2f = -0.5f * 1.44269504088896340736f * il2;
    const float T   = ETHR / c2f;               // dist^2 flag threshold

    const float* sZq = (const float*)(smem + SM_OFF_ZQ);
    const float* sAq = (const float*)(smem + SM_OFF_AQ);
    const int rBase = wm * 32 + (lane >> 2);
    const int nBase = wn * 32 + 2 * (lane & 3);

    float u[2][2];                              // rows rBase + mi*16 + {0,8}
#pragma unroll
    for (int mi = 0; mi < 2; mi++) {
        u[mi][0] = 0.5f * sZq[rBase + mi * 16]     - 0.25f * T;
        u[mi][1] = 0.5f * sZq[rBase + mi * 16 + 8] - 0.25f * T;
    }
    float v0[4], v1[4];                         // cols nBase + ni*8 + {0,1}
#pragma unroll
    for (int ni = 0; ni < 4; ni++) {
        v0[ni] = 0.5f * sAq[nBase + ni * 8]     - 0.25f * T;
        v1[ni] = 0.5f * sAq[nBase + ni * 8 + 1] - 0.25f * T;
    }

    int any_local = 0;
#pragma unroll
    for (int mi = 0; mi < 2; mi++)
#pragma unroll
        for (int ni = 0; ni < 4; ni++) {
            float2 p0 = __half22float2(*(const __half2*)&c[mi][ni][0]);
            float2 p1 = __half22float2(*(const __half2*)&c[mi][ni][1]);
            any_local |= (p0.x > u[mi][0] + v0[ni]) | (p0.y > u[mi][0] + v1[ni])
                       | (p1.x > u[mi][1] + v0[ni]) | (p1.y > u[mi][1] + v1[ni]);
        }

    // ~2.5e-5 spurious flag rate -> virtually every CTA exits here.
    if (!__syncthreads_or(any_local)) return;

    // Exact fp32 fallback over ALL 256 dims for flagged pairs (cold path).
#pragma unroll 1
    for (int mi = 0; mi < 2; mi++) {
#pragma unroll 1
        for (int ni = 0; ni < 4; ni++) {
#pragma unroll 1
            for (int q = 0; q < 4; q++) {
                int rl = rBase + mi * 16 + (q >> 1) * 8;
                int nl = nBase + ni * 8 + (q & 1);
                __half2 h = *(const __half2*)&c[mi][ni][q >> 1];
                float cr = (q & 1) ? __high2float(h) : __low2float(h);
                float ub = ((q >> 1) ? u[mi][1] : u[mi][0])
                         + ((q & 1) ? v1[ni] : v0[ni]);
                if (cr > ub) {
                    int gr = m0 + rl;
                    int gc = c0 + nl;
                    const float* zr = z    + (size_t)gr * LATENT;
                    const float* ar = anch + (size_t)gc * LATENT;
                    float dot = 0.f, zq = 0.f, aq = 0.f;
                    for (int k = 0; k < LATENT; k++) {
                        dot = fmaf(zr[k], ar[k], dot);
                        zq  = fmaf(zr[k], zr[k], zq);
                        aq  = fmaf(ar[k], ar[k], aq);
                    }
                    float de = fmaxf(zq + aq - 2.f * dot, 0.f);
                    float p  = expf(-0.5f * de * il2);
                    if (p != 0.f) {
                        const float* al = alpha + (size_t)gc * FDIM;
                        float*       o  = out   + (size_t)gr * FDIM;
                        for (int f = 0; f < FDIM; f++) atomicAdd(&o[f], p * al[f]);
                    }
                }
            }
        }
    }
}

// ---------------------------------------------------------------------------
extern "C" void kernel_launch(void* const* d_in, const int* in_sizes, int n_in,
                              void* d_out, int out_size) {
    const float* z     = (const float*)d_in[0];
    const float* anch  = (const float*)d_in[1];
    const float* alpha = (const float*)d_in[2];
    const float* logls = (const float*)d_in[3];
    float*       out   = (float*)d_out;

    cudaFuncSetAttribute(rkhs_main,
                         cudaFuncAttributeMaxDynamicSharedMemorySize, SMEM_DYN);

    // Merged zero + convert/norm prepass.
    int pblk = ((N_ROWS + N_ANCH) * 32 + 255) / 256;   // 4608
    rkhs_prep<<<ZBLK + pblk, 256>>>(z, anch, (float4*)d_out);

    dim3 grid(N_ANCH / BN, N_ROWS / BM);               // (32, 256)
    rkhs_main<<<grid, THREADS, SMEM_DYN>>>(z, anch, alpha, logls, out);
}